// round 12
// baseline (speedup 1.0000x reference)
#include <cuda_runtime.h>
#include <cuda_bf16.h>
#include <cstdint>
#include <cstddef>

#define T_STEPS 2048
#define BATCH   64
#define HID     256
#define INDIM   128
#define GJ      8      // j-slices per cluster (32 hidden units each)
#define GB      16     // batch-blocks (4 batches each)

// ---- scratch (device globals: allocation-free rule) ----
__device__ __align__(16) float g_xpart[(size_t)T_STEPS * BATCH * 4 * HID];   // 512 MB
__device__ __align__(16) float g_hst[BATCH * HID];   // final h

// ---------- helpers ----------
__device__ __forceinline__ float sigm(float x) {
    return __fdividef(1.f, 1.f + __expf(-x));
}
__device__ __forceinline__ float tanh_f(float x) {
    float e = __expf(2.f * x);
    return 1.f - __fdividef(2.f, e + 1.f);   // exact limits at +/-inf
}
__device__ __forceinline__ void ffma2(unsigned long long& d, unsigned long long a,
                                      unsigned long long b) {
    asm("fma.rn.f32x2 %0, %1, %2, %0;" : "+l"(d) : "l"(a), "l"(b));
}
__device__ __forceinline__ unsigned long long dup2(float x) {
    unsigned long long r;
    asm("mov.b64 %0, {%1, %1};" : "=l"(r) : "f"(x));
    return r;
}
__device__ __forceinline__ void unpack2(unsigned long long v, float& x, float& y) {
    asm("mov.b64 {%0, %1}, %2;" : "=f"(x), "=f"(y) : "l"(v));
}
__device__ __forceinline__ unsigned smem_u32(const void* p) {
    return (unsigned)__cvta_generic_to_shared(p);
}
__device__ __forceinline__ unsigned mapa_rank(unsigned local_addr, int rank) {
    unsigned r;
    asm("mapa.shared::cluster.u32 %0, %1, %2;" : "=r"(r) : "r"(local_addr), "r"(rank));
    return r;
}
__device__ __forceinline__ void st_cluster_v4(unsigned addr, float4 v) {
    asm volatile("st.shared::cluster.v4.b32 [%0], {%1, %2, %3, %4};"
                 :: "r"(addr), "f"(v.x), "f"(v.y), "f"(v.z), "f"(v.w) : "memory");
}
__device__ __forceinline__ void mbar_init(unsigned addr, unsigned count) {
    asm volatile("mbarrier.init.shared.b64 [%0], %1;" :: "r"(addr), "r"(count) : "memory");
}
__device__ __forceinline__ void mbar_arrive_rel_cluster(unsigned addr) {
    asm volatile("mbarrier.arrive.release.cluster.shared::cluster.b64 _, [%0];"
                 :: "r"(addr) : "memory");
}
__device__ __forceinline__ void mbar_wait_acq(unsigned addr, unsigned ph) {
    unsigned done;
    asm volatile(
        "{\n\t.reg .pred P;\n\t"
        "mbarrier.try_wait.parity.acquire.cluster.shared::cta.b64 P, [%1], %2;\n\t"
        "selp.b32 %0, 1, 0, P;\n\t}"
        : "=r"(done) : "r"(addr), "r"(ph) : "memory");
    if (!done) {
        asm volatile(
            "{\n\t.reg .pred P;\n"
            "W_%=:\n\t"
            "mbarrier.try_wait.parity.acquire.cluster.shared::cta.b64 P, [%0], %1, 0x989680;\n\t"
            "@P bra.uni D_%=;\n\t"
            "bra.uni W_%=;\n"
            "D_%=:\n\t}"
            :: "r"(addr), "r"(ph) : "memory");
    }
}
#define CLUSTER_ARRIVE() asm volatile("barrier.cluster.arrive.aligned;" ::: "memory")
#define CLUSTER_WAIT()   asm volatile("barrier.cluster.wait.aligned;"   ::: "memory")

// ---------- kernel 1: x_part GEMM with FUSED input gate + bias (R11, proven) ----------
__global__ void __launch_bounds__(256, 2) k_xpart(const float* __restrict__ xd,
                                                  const float* __restrict__ wg,
                                                  const float* __restrict__ Wih,
                                                  const float* __restrict__ bih,
                                                  const float* __restrict__ bhh) {
    __shared__ float As[32 * 132];   // [k][m] padded
    __shared__ float Bs[32 * 72];    // [k][n] padded

    const int tid = threadIdx.x;
    const int tx = tid & 15;
    const int ty = tid >> 4;
    const int m_base = blockIdx.y * 128;
    const int n_base = blockIdx.x * 64;

    unsigned long long acc[8][2];
#pragma unroll
    for (int i = 0; i < 8; ++i) { acc[i][0] = 0ull; acc[i][1] = 0ull; }

    const int am = tid & 127, ah = (tid >> 7) * 16;
    const int bn = tid & 63,  bh = (tid >> 6) * 8;
    const float* Xg = xd + (size_t)(m_base + am) * INDIM;   // rows m = b*T + t
    const float* Wg = wg + (size_t)(m_base + am) * INDIM;
    const float* Bg = Wih + (size_t)(n_base + bn) * INDIM;

    for (int ks = 0; ks < 4; ++ks) {
        const int k0 = ks * 32;
#pragma unroll
        for (int u = 0; u < 4; ++u) {
            float4 xv = __ldg((const float4*)(Xg + k0 + ah + u * 4));
            float4 wv = __ldg((const float4*)(Wg + k0 + ah + u * 4));
            int k = ah + u * 4;
            As[(k + 0) * 132 + am] = xv.x * sigm(wv.x);
            As[(k + 1) * 132 + am] = xv.y * sigm(wv.y);
            As[(k + 2) * 132 + am] = xv.z * sigm(wv.z);
            As[(k + 3) * 132 + am] = xv.w * sigm(wv.w);
        }
#pragma unroll
        for (int u = 0; u < 2; ++u) {
            float4 v = __ldg((const float4*)(Bg + k0 + bh + u * 4));
            int k = bh + u * 4;
            Bs[(k + 0) * 72 + bn] = v.x;
            Bs[(k + 1) * 72 + bn] = v.y;
            Bs[(k + 2) * 72 + bn] = v.z;
            Bs[(k + 3) * 72 + bn] = v.w;
        }
        __syncthreads();
#pragma unroll
        for (int k = 0; k < 32; ++k) {
            const ulonglong2 bbv = *(const ulonglong2*)&Bs[k * 72 + tx * 4];
            const float4 a0 = *(const float4*)&As[k * 132 + ty * 8];
            const float4 a1 = *(const float4*)&As[k * 132 + ty * 8 + 4];
            float a[8] = {a0.x, a0.y, a0.z, a0.w, a1.x, a1.y, a1.z, a1.w};
#pragma unroll
            for (int i = 0; i < 8; ++i) {
                unsigned long long d = dup2(a[i]);
                ffma2(acc[i][0], d, bbv.x);
                ffma2(acc[i][1], d, bbv.y);
            }
        }
        __syncthreads();
    }

    const int col0 = n_base + tx * 4;
    float4 bias;
    bias.x = __ldg(bih + col0 + 0) + __ldg(bhh + col0 + 0);
    bias.y = __ldg(bih + col0 + 1) + __ldg(bhh + col0 + 1);
    bias.z = __ldg(bih + col0 + 2) + __ldg(bhh + col0 + 2);
    bias.w = __ldg(bih + col0 + 3) + __ldg(bhh + col0 + 3);
#pragma unroll
    for (int i = 0; i < 8; ++i) {
        int gm = m_base + ty * 8 + i;
        int b = gm >> 11;              // m = b*2048 + t
        int t = gm & 2047;
        float x0, x1, x2, x3;
        unpack2(acc[i][0], x0, x1);
        unpack2(acc[i][1], x2, x3);
        float4 o = make_float4(x0 + bias.x, x1 + bias.y, x2 + bias.z, x3 + bias.w);
        *(float4*)&g_xpart[((size_t)t * BATCH + b) * (4 * HID) + col0] = o;
    }
}

// ---------- kernel 2: persistent LSTM recurrence, TWO streams per CTA ----------
// 128 CTAs of 512 threads, clusters of 8 (rank jb), bb = blockIdx>>3.
// Stream A = batches bb*4+{0,1}; stream B = bb*4+{2,3}. Each stream has its
// own h ping-pong buffers and 2-slot mbar rendezvous ring; A's exchange
// flight is covered by B's compute and vice versa (wait deferred to just
// before the consuming stream's FMA in the NEXT iteration).
// Thread: kc = tid&15 (k = 2kc+32m), rg = tid>>4 (local j).
__global__ void __launch_bounds__(512, 1) __cluster_dims__(GJ, 1, 1)
k_rec(const float* __restrict__ Whh) {
    const int tid = threadIdx.x;
    const int kc = tid & 15;
    const int rg = tid >> 4;
    const int lane = tid & 31;
    const int wrp = tid >> 5;
    unsigned jb;
    asm("mov.u32 %0, %%cluster_ctarank;" : "=r"(jb));
    const int bb = blockIdx.x >> 3;

    // per-stream: [slot][rank(8)][b(2)][k32] = 512 floats (2KB)/slot
    __shared__ __align__(16) float bufA[2][GJ * 2 * 32];
    __shared__ __align__(16) float bufB[2][GJ * 2 * 32];
    __shared__ __align__(16) float xpsA[256];     // [b(2)][g(4)][j(32)]
    __shared__ __align__(16) float xpsB[256];
    __shared__ __align__(16) float stgA[64];      // [b(2)][j(32)]
    __shared__ __align__(16) float stgB[64];
    __shared__ __align__(8)  unsigned long long mbA[2], mbB[2];

    // persistent W registers (shared by both streams):
    // w2[g][m] = (W[g*256+jb*32+rg][2kc+32m], [..+1])
    unsigned long long w2[4][8];
#pragma unroll
    for (int g = 0; g < 4; ++g) {
        const float* rp = Whh + (size_t)(g * HID + jb * 32 + rg) * HID + 2 * kc;
#pragma unroll
        for (int m = 0; m < 8; ++m)
            w2[g][m] = __ldg((const unsigned long long*)(rp + 32 * m));
    }

    // h(0) = 0 in slot 0 of both streams
#pragma unroll
    for (int i = tid; i < GJ * 2 * 32; i += 512) { bufA[0][i] = 0.f; bufB[0][i] = 0.f; }
    if (tid == 0) {
        mbar_init(smem_u32(&mbA[0]), GJ);
        mbar_init(smem_u32(&mbA[1]), GJ);
        mbar_init(smem_u32(&mbB[0]), GJ);
        mbar_init(smem_u32(&mbB[1]), GJ);
    }

    float cA = 0.f, cB = 0.f;      // owner cell states (kc<2: b = kc)

    // copier setup: warp w<8 ships 256B (lanes 0-15) to dest rank w
    const bool is_local = (wrp == (int)jb);
    unsigned rdA = 0, rdB = 0;
    if (wrp < GJ) {
        rdA = mapa_rank(smem_u32(&bufA[0][0]), wrp) + jb * 256u + lane * 16u;
        rdB = mapa_rank(smem_u32(&bufB[0][0]), wrp) + jb * 256u + lane * 16u;
    }
    float* ldA = &bufA[0][jb * 64 + lane * 4];
    float* ldB = &bufB[0][jb * 64 + lane * 4];

    // remote mbar addresses for arrivals (tid<8 arrives at rank tid)
    unsigned rmA0 = 0, rmA1 = 0, rmB0 = 0, rmB1 = 0;
    if (tid < GJ) {
        rmA0 = mapa_rank(smem_u32(&mbA[0]), tid);
        rmA1 = mapa_rank(smem_u32(&mbA[1]), tid);
        rmB0 = mapa_rank(smem_u32(&mbB[0]), tid);
        rmB1 = mapa_rank(smem_u32(&mbB[1]), tid);
    }
    const unsigned wlA0 = smem_u32(&mbA[0]), wlA1 = smem_u32(&mbA[1]);
    const unsigned wlB0 = smem_u32(&mbB[0]), wlB1 = smem_u32(&mbB[1]);

    __syncthreads();
    CLUSTER_ARRIVE();          // mbar init + buf zero visible cluster-wide
    CLUSTER_WAIT();

    // xp: thread covers one scalar per stream-half: s = tid>>8 selects stream
    const int s  = tid >> 8;               // 0 → A, 1 → B
    const int q  = tid & 255;
    const int xb = q >> 7, xg2 = (q >> 5) & 3, xj = q & 31;
    const float* xcur = g_xpart + (size_t)(bb * 4 + s * 2 + xb) * (4 * HID)
                      + xg2 * HID + jb * 32 + xj;
    const size_t tstride = (size_t)BATCH * 4 * HID;
    float xp_pf = __ldg(xcur);             // xp(t=0)

    const bool u1 = (kc & 1), u2 = (kc & 2), u4 = (kc & 4);
    const bool owner = (kc < 2);
    const int ob = kc & 1;                 // owner batch within stream

    int p = 0;                             // shared slot parity (A and B in sync)
    for (int t = 0; t < T_STEPS; ++t) {
        // stage xp(t) for my stream (readers gated by S1)
        (s ? xpsB : xpsA)[q] = xp_pf;

        const unsigned wslot = (t - 1) & 1;            // wait slot for t>=1
        const unsigned wph   = (unsigned)(((t - 1) >> 1) & 1);

        // ================= stream A =================
        float zA, fA, gA, oA;
        {
            if (t) mbar_wait_acq(wslot ? wlA1 : wlA0, wph);
            unsigned long long acc[4][2];
#pragma unroll
            for (int g = 0; g < 4; ++g) { acc[g][0] = 0ull; acc[g][1] = 0ull; }
            const float* hb = &bufA[p][0];
#pragma unroll
            for (int m = 0; m < 8; ++m)
#pragma unroll
                for (int b = 0; b < 2; ++b) {
                    unsigned long long h2 =
                        *(const unsigned long long*)&hb[(m * 2 + b) * 32 + 2 * kc];
#pragma unroll
                    for (int g = 0; g < 4; ++g) ffma2(acc[g][b], w2[g][m], h2);
                }
            // horizontal add: v[i], i = g*2+b (8 values over 16 kc lanes)
            float v[8];
#pragma unroll
            for (int g = 0; g < 4; ++g)
#pragma unroll
                for (int b = 0; b < 2; ++b) {
                    float lo, hi;
                    unpack2(acc[g][b], lo, hi);
                    v[g * 2 + b] = lo + hi;
                }
            float u[4];
#pragma unroll
            for (int j = 0; j < 4; ++j) {
                float snd = u1 ? v[2 * j] : v[2 * j + 1];
                float kept = u1 ? v[2 * j + 1] : v[2 * j];
                u[j] = kept + __shfl_xor_sync(0xffffffffu, snd, 1);
            }
            float w4[2];
#pragma unroll
            for (int j = 0; j < 2; ++j) {
                float snd = u2 ? u[2 * j] : u[2 * j + 1];
                float kept = u2 ? u[2 * j + 1] : u[2 * j];
                w4[j] = kept + __shfl_xor_sync(0xffffffffu, snd, 2);
            }
            float x1;
            {
                float snd = u4 ? w4[0] : w4[1];
                float kept = u4 ? w4[1] : w4[0];
                x1 = kept + __shfl_xor_sync(0xffffffffu, snd, 4);
            }
            zA = x1 + __shfl_xor_sync(0xffffffffu, x1, 8);   // z[idx = kc&7]
            fA = __shfl_xor_sync(0xffffffffu, zA, 2);        // idx b ↔ 2+b
            gA = __shfl_xor_sync(0xffffffffu, zA, 4);        // 4+b
            oA = __shfl_xor_sync(0xffffffffu, fA, 4);        // 6+b
        }
        __syncthreads();   // S1: xp staged visible; bufA[p] reads complete

        if (owner) {       // gates A: (b = ob, j = jb*32+rg)
            float zi = zA + xpsA[(ob * 4 + 0) * 32 + rg];
            float zf = fA + xpsA[(ob * 4 + 1) * 32 + rg];
            float zg = gA + xpsA[(ob * 4 + 2) * 32 + rg];
            float zo = oA + xpsA[(ob * 4 + 3) * 32 + rg];
            cA = sigm(zf) * cA + sigm(zi) * tanh_f(zg);
            float h = sigm(zo) * tanh_f(cA);
            stgA[ob * 32 + rg] = h;
            if (t == T_STEPS - 1)
                g_hst[bb * 1024 + ob * HID + jb * 32 + rg] = h;
        }
        __syncthreads();   // S2: stgA ready

        if (wrp < GJ && lane < 16) {   // exch A → dest bufA[p^1]
            float4 hv = *(const float4*)&stgA[lane * 4];
            const unsigned poff = (unsigned)((p ^ 1) * (GJ * 2 * 32) * 4);
            if (is_local) *(float4*)((char*)ldA + poff) = hv;
            else          st_cluster_v4(rdA + poff, hv);
        }

        // ================= stream B =================
        float zB, fB, gB, oB;
        {
            if (t) mbar_wait_acq(wslot ? wlB1 : wlB0, wph);
            unsigned long long acc[4][2];
#pragma unroll
            for (int g = 0; g < 4; ++g) { acc[g][0] = 0ull; acc[g][1] = 0ull; }
            const float* hb = &bufB[p][0];
#pragma unroll
            for (int m = 0; m < 8; ++m)
#pragma unroll
                for (int b = 0; b < 2; ++b) {
                    unsigned long long h2 =
                        *(const unsigned long long*)&hb[(m * 2 + b) * 32 + 2 * kc];
#pragma unroll
                    for (int g = 0; g < 4; ++g) ffma2(acc[g][b], w2[g][m], h2);
                }
            float v[8];
#pragma unroll
            for (int g = 0; g < 4; ++g)
#pragma unroll
                for (int b = 0; b < 2; ++b) {
                    float lo, hi;
                    unpack2(acc[g][b], lo, hi);
                    v[g * 2 + b] = lo + hi;
                }
            float u[4];
#pragma unroll
            for (int j = 0; j < 4; ++j) {
                float snd = u1 ? v[2 * j] : v[2 * j + 1];
                float kept = u1 ? v[2 * j + 1] : v[2 * j];
                u[j] = kept + __shfl_xor_sync(0xffffffffu, snd, 1);
            }
            float w4[2];
#pragma unroll
            for (int j = 0; j < 2; ++j) {
                float snd = u2 ? u[2 * j] : u[2 * j + 1];
                float kept = u2 ? u[2 * j + 1] : u[2 * j];
                w4[j] = kept + __shfl_xor_sync(0xffffffffu, snd, 2);
            }
            float x1;
            {
                float snd = u4 ? w4[0] : w4[1];
                float kept = u4 ? w4[1] : w4[0];
                x1 = kept + __shfl_xor_sync(0xffffffffu, snd, 4);
            }
            zB = x1 + __shfl_xor_sync(0xffffffffu, x1, 8);
            fB = __shfl_xor_sync(0xffffffffu, zB, 2);
            gB = __shfl_xor_sync(0xffffffffu, zB, 4);
            oB = __shfl_xor_sync(0xffffffffu, fB, 4);
        }
        __syncthreads();   // S3: bufB[p] reads complete; drains A's DSMEM stores

        // arrive for A (stores drained by S3); peers' waitA fires next iter
        if (tid < GJ) mbar_arrive_rel_cluster((t & 1) ? rmA1 : rmA0);

        if (owner) {       // gates B (xpsB visible since S1)
            float zi = zB + xpsB[(ob * 4 + 0) * 32 + rg];
            float zf = fB + xpsB[(ob * 4 + 1) * 32 + rg];
            float zg = gB + xpsB[(ob * 4 + 2) * 32 + rg];
            float zo = oB + xpsB[(ob * 4 + 3) * 32 + rg];
            cB = sigm(zf) * cB + sigm(zi) * tanh_f(zg);
            float h = sigm(zo) * tanh_f(cB);
            stgB[ob * 32 + rg] = h;
            if (t == T_STEPS - 1)
                g_hst[bb * 1024 + (2 + ob) * HID + jb * 32 + rg] = h;
        }
        __syncthreads();   // S4: stgB ready

        if (wrp < GJ && lane < 16) {   // exch B → dest bufB[p^1]
            float4 hv = *(const float4*)&stgB[lane * 4];
            const unsigned poff = (unsigned)((p ^ 1) * (GJ * 2 * 32) * 4);
            if (is_local) *(float4*)((char*)ldB + poff) = hv;
            else          st_cluster_v4(rdB + poff, hv);
        }
        __syncthreads();   // S5: drains B's DSMEM stores

        if (tid < GJ) mbar_arrive_rel_cluster((t & 1) ? rmB1 : rmB0);

        // prefetch next xp during the open window
        if (t < T_STEPS - 1) {
            xcur += tstride;
            xp_pf = __ldg(xcur);
        }
        p ^= 1;
    }

    // no CTA may exit while peers' DSMEM stores/arrives may target its smem
    CLUSTER_ARRIVE();
    CLUSTER_WAIT();
}

// ---------- kernel 3: out[b] = h_T[b] @ W_out^T + b_out ----------
__global__ void __launch_bounds__(256) k_out(const float* __restrict__ Wout,
                                             const float* __restrict__ bout,
                                             float* __restrict__ out) {
    const int b = blockIdx.x;
    const int tid = threadIdx.x;
    float v = g_hst[b * HID + tid] * __ldg(Wout + tid);
#pragma unroll
    for (int d = 16; d >= 1; d >>= 1) v += __shfl_xor_sync(0xffffffffu, v, d);
    __shared__ float s[8];
    if ((tid & 31) == 0) s[tid >> 5] = v;
    __syncthreads();
    if (tid == 0) {
        float acc = 0.f;
#pragma unroll
        for (int i = 0; i < 8; ++i) acc += s[i];
        out[b] = acc + __ldg(bout);
    }
}

// ---------- launch ----------
extern "C" void kernel_launch(void* const* d_in, const int* in_sizes, int n_in,
                              void* d_out, int out_size) {
    const float* xd   = (const float*)d_in[0];
    const float* w    = (const float*)d_in[1];
    const float* Wih  = (const float*)d_in[2];
    const float* bih  = (const float*)d_in[3];
    const float* Whh  = (const float*)d_in[4];
    const float* bhh  = (const float*)d_in[5];
    const float* Wout = (const float*)d_in[6];
    const float* bout = (const float*)d_in[7];
    float* out = (float*)d_out;

    dim3 gx(1024 / 64, (BATCH * T_STEPS) / 128);
    k_xpart<<<gx, 256>>>(xd, w, Wih, bih, bhh);   // fused input gate

    k_rec<<<GJ * GB, 512>>>(Whh);   // 128 CTAs, 16 clusters of 8, 2 streams/CTA

    k_out<<<BATCH, 256>>>(Wout, bout, out);
}

// round 13
// speedup vs baseline: 1.2771x; 1.2771x over previous
#include <cuda_runtime.h>
#include <cuda_bf16.h>
#include <cstdint>
#include <cstddef>

#define T_STEPS 2048
#define BATCH   64
#define HID     256
#define INDIM   128
#define GJ      8      // j-slices per cluster (32 hidden units each)
#define GB      16     // batch-blocks (4 batches each)
#define CHUNK   512    // steps per k_rec launch
#define NCHUNK  (T_STEPS / CHUNK)

// ---- scratch (device globals: allocation-free rule) ----
__device__ __align__(16) float g_xpart[(size_t)T_STEPS * BATCH * 4 * HID];   // 512 MB
__device__ __align__(16) float g_hst[BATCH * HID];   // h at chunk boundaries / final
__device__ __align__(16) float g_cst[BATCH * HID];   // c at chunk boundaries

// ---------- helpers ----------
__device__ __forceinline__ float sigm(float x) {
    return __fdividef(1.f, 1.f + __expf(-x));
}
__device__ __forceinline__ float tanh_f(float x) {
    float e = __expf(2.f * x);
    return 1.f - __fdividef(2.f, e + 1.f);   // exact limits at +/-inf
}
__device__ __forceinline__ void ffma2(unsigned long long& d, unsigned long long a,
                                      unsigned long long b) {
    asm("fma.rn.f32x2 %0, %1, %2, %0;" : "+l"(d) : "l"(a), "l"(b));
}
__device__ __forceinline__ unsigned long long dup2(float x) {
    unsigned long long r;
    asm("mov.b64 %0, {%1, %1};" : "=l"(r) : "f"(x));
    return r;
}
__device__ __forceinline__ void unpack2(unsigned long long v, float& x, float& y) {
    asm("mov.b64 {%0, %1}, %2;" : "=f"(x), "=f"(y) : "l"(v));
}
__device__ __forceinline__ unsigned smem_u32(const void* p) {
    return (unsigned)__cvta_generic_to_shared(p);
}
__device__ __forceinline__ unsigned mapa_rank(unsigned local_addr, int rank) {
    unsigned r;
    asm("mapa.shared::cluster.u32 %0, %1, %2;" : "=r"(r) : "r"(local_addr), "r"(rank));
    return r;
}
__device__ __forceinline__ void st_cluster_v4(unsigned addr, float4 v) {
    asm volatile("st.shared::cluster.v4.b32 [%0], {%1, %2, %3, %4};"
                 :: "r"(addr), "f"(v.x), "f"(v.y), "f"(v.z), "f"(v.w) : "memory");
}
#define CLUSTER_ARRIVE() asm volatile("barrier.cluster.arrive.aligned;" ::: "memory")
#define CLUSTER_WAIT()   asm volatile("barrier.cluster.wait.aligned;"   ::: "memory")

// ---------- kernel 1: x_part GEMM, fused input gate, m-packed f32x2 ----------
// x_part[t][b][col] = (xd[b][t][:] * sigm(w[b][t][:])) @ Wih^T + (bih + bhh)
// Thread tile 8m x 4n; accumulators pack m-PAIRS (a-pairs load straight from
// As[k][m]); only 4 dup-MOVs per k (one per n) instead of 8.
__global__ void __launch_bounds__(256, 2) k_xpart(const float* __restrict__ xd,
                                                  const float* __restrict__ wg,
                                                  const float* __restrict__ Wih,
                                                  const float* __restrict__ bih,
                                                  const float* __restrict__ bhh) {
    __shared__ float As[32 * 132];   // [k][m] padded
    __shared__ float Bs[32 * 72];    // [k][n] padded

    const int tid = threadIdx.x;
    const int tx = tid & 15;         // n quad
    const int ty = tid >> 4;         // m group (8 m each)
    const int m_base = blockIdx.y * 128;
    const int n_base = blockIdx.x * 64;

    // acc[mp][n]: packed (m=2mp, m=2mp+1) results for column n
    unsigned long long acc[4][4];
#pragma unroll
    for (int i = 0; i < 4; ++i)
#pragma unroll
        for (int j = 0; j < 4; ++j) acc[i][j] = 0ull;

    const int am = tid & 127, ah = (tid >> 7) * 16;
    const int bn = tid & 63,  bh = (tid >> 6) * 8;
    const float* Xg = xd + (size_t)(m_base + am) * INDIM;   // rows m = b*T + t
    const float* Wg = wg + (size_t)(m_base + am) * INDIM;
    const float* Bg = Wih + (size_t)(n_base + bn) * INDIM;

    for (int ks = 0; ks < 4; ++ks) {
        const int k0 = ks * 32;
#pragma unroll
        for (int u = 0; u < 4; ++u) {
            float4 xv = __ldg((const float4*)(Xg + k0 + ah + u * 4));
            float4 wv = __ldg((const float4*)(Wg + k0 + ah + u * 4));
            int k = ah + u * 4;
            As[(k + 0) * 132 + am] = xv.x * sigm(wv.x);
            As[(k + 1) * 132 + am] = xv.y * sigm(wv.y);
            As[(k + 2) * 132 + am] = xv.z * sigm(wv.z);
            As[(k + 3) * 132 + am] = xv.w * sigm(wv.w);
        }
#pragma unroll
        for (int u = 0; u < 2; ++u) {
            float4 v = __ldg((const float4*)(Bg + k0 + bh + u * 4));
            int k = bh + u * 4;
            Bs[(k + 0) * 72 + bn] = v.x;
            Bs[(k + 1) * 72 + bn] = v.y;
            Bs[(k + 2) * 72 + bn] = v.z;
            Bs[(k + 3) * 72 + bn] = v.w;
        }
        __syncthreads();
#pragma unroll
        for (int k = 0; k < 32; ++k) {
            const ulonglong2 a01 = *(const ulonglong2*)&As[k * 132 + ty * 8];
            const ulonglong2 a23 = *(const ulonglong2*)&As[k * 132 + ty * 8 + 4];
            const float4 bv = *(const float4*)&Bs[k * 72 + tx * 4];
            unsigned long long bd0 = dup2(bv.x);
            unsigned long long bd1 = dup2(bv.y);
            unsigned long long bd2 = dup2(bv.z);
            unsigned long long bd3 = dup2(bv.w);
            ffma2(acc[0][0], a01.x, bd0);
            ffma2(acc[0][1], a01.x, bd1);
            ffma2(acc[0][2], a01.x, bd2);
            ffma2(acc[0][3], a01.x, bd3);
            ffma2(acc[1][0], a01.y, bd0);
            ffma2(acc[1][1], a01.y, bd1);
            ffma2(acc[1][2], a01.y, bd2);
            ffma2(acc[1][3], a01.y, bd3);
            ffma2(acc[2][0], a23.x, bd0);
            ffma2(acc[2][1], a23.x, bd1);
            ffma2(acc[2][2], a23.x, bd2);
            ffma2(acc[2][3], a23.x, bd3);
            ffma2(acc[3][0], a23.y, bd0);
            ffma2(acc[3][1], a23.y, bd1);
            ffma2(acc[3][2], a23.y, bd2);
            ffma2(acc[3][3], a23.y, bd3);
        }
        __syncthreads();
    }

    const int col0 = n_base + tx * 4;
    float4 bias;
    bias.x = __ldg(bih + col0 + 0) + __ldg(bhh + col0 + 0);
    bias.y = __ldg(bih + col0 + 1) + __ldg(bhh + col0 + 1);
    bias.z = __ldg(bih + col0 + 2) + __ldg(bhh + col0 + 2);
    bias.w = __ldg(bih + col0 + 3) + __ldg(bhh + col0 + 3);
#pragma unroll
    for (int mp = 0; mp < 4; ++mp) {
        float l0, h0, l1, h1, l2, h2, l3, h3;
        unpack2(acc[mp][0], l0, h0);
        unpack2(acc[mp][1], l1, h1);
        unpack2(acc[mp][2], l2, h2);
        unpack2(acc[mp][3], l3, h3);
        int gm0 = m_base + ty * 8 + 2 * mp;          // m = b*2048 + t
        int b0 = gm0 >> 11, t0 = gm0 & 2047;
        int b1 = (gm0 + 1) >> 11, t1 = (gm0 + 1) & 2047;
        *(float4*)&g_xpart[((size_t)t0 * BATCH + b0) * (4 * HID) + col0] =
            make_float4(l0 + bias.x, l1 + bias.y, l2 + bias.z, l3 + bias.w);
        *(float4*)&g_xpart[((size_t)t1 * BATCH + b1) * (4 * HID) + col0] =
            make_float4(h0 + bias.x, h1 + bias.y, h2 + bias.z, h3 + bias.w);
    }
}

// ---------- kernel 2: LSTM recurrence chunk (EXACT Round-6 best, 8419.8us) ----------
// 128 CTAs of 512 threads, clusters of 8 (rank jb = j-slice), bb = blockIdx>>3.
// Thread: rg = tid>>4 (local j), kc = tid&15 (16 k-slices, k = 2kc+32m, m<8).
// buf layout: [p][rank][b][j32]; exchange = one warp-wide 512B store per dest.
__global__ void __launch_bounds__(512, 1) __cluster_dims__(GJ, 1, 1)
k_rec(const float* __restrict__ Whh, int chunk) {
    const int tid = threadIdx.x;
    const int kc = tid & 15;
    const int rg = tid >> 4;
    unsigned jb;
    asm("mov.u32 %0, %%cluster_ctarank;" : "=r"(jb));
    const int bb = blockIdx.x >> 3;

    __shared__ __align__(16) float buf[2][GJ * 4 * 32];  // [p][rank][b][j] (2 x 4KB)
    __shared__ __align__(16) float xp_s[512];            // [b][g][j]
    __shared__ __align__(16) float staging[128];         // [b][j] local h slice

    // persistent W registers: w2[g][m] = (W[row][2kc+32m], W[row][2kc+32m+1])
    unsigned long long w2[4][8];
#pragma unroll
    for (int g = 0; g < 4; ++g) {
        const float* rp = Whh + (size_t)(g * HID + jb * 32 + rg) * HID + 2 * kc;
#pragma unroll
        for (int m = 0; m < 8; ++m)
            w2[g][m] = __ldg((const unsigned long long*)(rp + 32 * m));
    }

    // h(chunk start) into buf[0] in [rank][b][j] layout
#pragma unroll
    for (int i = tid; i < GJ * 4 * 32; i += 512) {
        int r = i >> 7, b = (i >> 5) & 3, j = i & 31;
        buf[0][i] = (chunk == 0) ? 0.f
                                 : __ldcg(&g_hst[bb * 1024 + b * HID + r * 32 + j]);
    }

    // owner cell state
    const int ob = kc & 3;                     // owner batch (valid when kc<4)
    const size_t cell = (size_t)bb * 1024 + (size_t)ob * HID + jb * 32 + rg;
    float c = 0.f;
    if (chunk != 0 && kc < 4) c = __ldcg(&g_cst[cell]);

    // copier setup: warp w<8 copies staging (512B) to dest rank w's buf slot
    const int wrp = tid >> 5, lane = tid & 31;
    unsigned rdst = 0;
    if (wrp < GJ)
        rdst = mapa_rank(smem_u32(&buf[0][0]), wrp) + jb * 512u + lane * 16u;

    __syncthreads();
    CLUSTER_ARRIVE();
    CLUSTER_WAIT();

    // xp mapping: tid = b*128 + g*32 + j  → xp_s[tid]
    const int t0 = chunk * CHUNK;
    const int xb = tid >> 7, xg = (tid >> 5) & 3, xj = tid & 31;
    const float* xptr = g_xpart + (size_t)(bb * 4 + xb) * (4 * HID) + xg * HID + jb * 32 + xj;
    float xp_pf = __ldg(xptr + (size_t)t0 * (BATCH * 4 * HID));

    const bool u1 = (kc & 1), u2 = (kc & 2), u4 = (kc & 4), u8 = (kc & 8);

    int p = 0;
    for (int t = 0; t < CHUNK; ++t) {
        // stage xp for this step (readers wait for the syncthreads below;
        // prior-step readers all passed last step's barriers, so no race)
        xp_s[tid] = xp_pf;

        // ---- z_hh partial GEMM over local h copy ----
        unsigned long long acc[4][4];
#pragma unroll
        for (int g = 0; g < 4; ++g)
#pragma unroll
            for (int b = 0; b < 4; ++b) acc[g][b] = 0ull;

        const float* hb = &buf[p][0];
#pragma unroll
        for (int m = 0; m < 8; ++m) {
#pragma unroll
            for (int b = 0; b < 4; ++b) {
                unsigned long long h2 =
                    *(const unsigned long long*)&hb[(m * 4 + b) * 32 + 2 * kc];
#pragma unroll
                for (int g = 0; g < 4; ++g) ffma2(acc[g][b], w2[g][m], h2);
            }
        }

        // ---- horizontal add: v[i], i = g*4+b ----
        float v[16];
#pragma unroll
        for (int g = 0; g < 4; ++g)
#pragma unroll
            for (int b = 0; b < 4; ++b) {
                float lo, hi;
                unpack2(acc[g][b], lo, hi);
                v[g * 4 + b] = lo + hi;
            }

        // ---- split-tree reduction over 16 kc lanes ----
        float u[8];
#pragma unroll
        for (int j = 0; j < 8; ++j) {
            float snd = u1 ? v[2 * j] : v[2 * j + 1];
            float kept = u1 ? v[2 * j + 1] : v[2 * j];
            u[j] = kept + __shfl_xor_sync(0xffffffffu, snd, 1);
        }
        float w4[4];
#pragma unroll
        for (int j = 0; j < 4; ++j) {
            float snd = u2 ? u[2 * j] : u[2 * j + 1];
            float kept = u2 ? u[2 * j + 1] : u[2 * j];
            w4[j] = kept + __shfl_xor_sync(0xffffffffu, snd, 2);
        }
        float x2[2];
#pragma unroll
        for (int j = 0; j < 2; ++j) {
            float snd = u4 ? w4[2 * j] : w4[2 * j + 1];
            float kept = u4 ? w4[2 * j + 1] : w4[2 * j];
            x2[j] = kept + __shfl_xor_sync(0xffffffffu, snd, 4);
        }
        float z;                                   // z[g=kc>>2][b=kc&3]
        {
            float snd = u8 ? x2[0] : x2[1];
            float kept = u8 ? x2[1] : x2[0];
            z = kept + __shfl_xor_sync(0xffffffffu, snd, 8);
        }
        // gather gates onto owner lanes (kc<4): i,f,g,o
        float t1 = __shfl_xor_sync(0xffffffffu, z, 4);
        float t2 = __shfl_xor_sync(0xffffffffu, z, 8);
        float t3 = __shfl_xor_sync(0xffffffffu, t1, 8);

        __syncthreads();   // sync#1: xp_s visible to owners

        // ---- cell update (owners) → local staging ----
        if (kc < 4) {
            float zi = z  + xp_s[(ob * 4 + 0) * 32 + rg];
            float zf = t1 + xp_s[(ob * 4 + 1) * 32 + rg];
            float zg = t2 + xp_s[(ob * 4 + 2) * 32 + rg];
            float zo = t3 + xp_s[(ob * 4 + 3) * 32 + rg];
            c = sigm(zf) * c + sigm(zi) * tanh_f(zg);
            float h = sigm(zo) * tanh_f(c);
            staging[ob * 32 + rg] = h;
            if (t == CHUNK - 1) {
                g_hst[cell] = h;
                g_cst[cell] = c;
            }
        }
        __syncthreads();   // sync#2: staging complete

        // ---- bulk exchange: warp w ships 512B slice to dest rank w ----
        if (wrp < GJ) {
            float4 hv = *(const float4*)&staging[lane * 4];
            st_cluster_v4(rdst + (unsigned)((p ^ 1) * (GJ * 4 * 32) * 4), hv);
        }

        // ---- barrier: arrive (releases copier stores), prefetch, wait ----
        CLUSTER_ARRIVE();
        {
            int tn = t0 + t + 1;
            if (tn > T_STEPS - 1) tn = T_STEPS - 1;
            xp_pf = __ldg(xptr + (size_t)tn * (BATCH * 4 * HID));
        }
        CLUSTER_WAIT();
        p ^= 1;
    }
}

// ---------- kernel 3: out[b] = h_T[b] @ W_out^T + b_out ----------
__global__ void __launch_bounds__(256) k_out(const float* __restrict__ Wout,
                                             const float* __restrict__ bout,
                                             float* __restrict__ out) {
    const int b = blockIdx.x;
    const int tid = threadIdx.x;
    float v = g_hst[b * HID + tid] * __ldg(Wout + tid);
#pragma unroll
    for (int d = 16; d >= 1; d >>= 1) v += __shfl_xor_sync(0xffffffffu, v, d);
    __shared__ float s[8];
    if ((tid & 31) == 0) s[tid >> 5] = v;
    __syncthreads();
    if (tid == 0) {
        float acc = 0.f;
#pragma unroll
        for (int i = 0; i < 8; ++i) acc += s[i];
        out[b] = acc + __ldg(bout);
    }
}

// ---------- launch ----------
extern "C" void kernel_launch(void* const* d_in, const int* in_sizes, int n_in,
                              void* d_out, int out_size) {
    const float* xd   = (const float*)d_in[0];
    const float* w    = (const float*)d_in[1];
    const float* Wih  = (const float*)d_in[2];
    const float* bih  = (const float*)d_in[3];
    const float* Whh  = (const float*)d_in[4];
    const float* bhh  = (const float*)d_in[5];
    const float* Wout = (const float*)d_in[6];
    const float* bout = (const float*)d_in[7];
    float* out = (float*)d_out;

    dim3 gx(1024 / 64, (BATCH * T_STEPS) / 128);
    k_xpart<<<gx, 256>>>(xd, w, Wih, bih, bhh);   // fused gate, m-packed f32x2

    for (int c = 0; c < NCHUNK; ++c)
        k_rec<<<GJ * GB, 512>>>(Whh, c);   // 128 CTAs, 16 clusters of 8

    k_out<<<BATCH, 256>>>(Wout, bout, out);
}

// round 14
// speedup vs baseline: 1.3004x; 1.0183x over previous
#include <cuda_runtime.h>
#include <cuda_bf16.h>
#include <cstdint>
#include <cstddef>

#define T_STEPS 2048
#define BATCH   64
#define HID     256
#define INDIM   128
#define GJ      8      // j-slices per cluster (32 hidden units each)
#define GB      16     // batch-blocks (4 batches each)
#define CHUNK   2048   // single launch: all steps in one k_rec
#define NCHUNK  (T_STEPS / CHUNK)

// ---- scratch (device globals: allocation-free rule) ----
__device__ __align__(16) float g_gated[(size_t)BATCH * T_STEPS * INDIM];       // 64 MB
__device__ __align__(16) float g_xpart[(size_t)T_STEPS * BATCH * 4 * HID];     // 512 MB
__device__ __align__(16) float g_hst[BATCH * HID];   // final h
__device__ __align__(16) float g_cst[BATCH * HID];   // (unused in single-chunk mode)

// ---------- helpers ----------
__device__ __forceinline__ float sigm(float x) {
    return __fdividef(1.f, 1.f + __expf(-x));
}
__device__ __forceinline__ float tanh_f(float x) {
    float e = __expf(2.f * x);
    return 1.f - __fdividef(2.f, e + 1.f);   // exact limits at +/-inf
}
__device__ __forceinline__ void ffma2(unsigned long long& d, unsigned long long a,
                                      unsigned long long b) {
    asm("fma.rn.f32x2 %0, %1, %2, %0;" : "+l"(d) : "l"(a), "l"(b));
}
__device__ __forceinline__ unsigned long long dup2(float x) {
    unsigned long long r;
    asm("mov.b64 %0, {%1, %1};" : "=l"(r) : "f"(x));
    return r;
}
__device__ __forceinline__ void unpack2(unsigned long long v, float& x, float& y) {
    asm("mov.b64 {%0, %1}, %2;" : "=f"(x), "=f"(y) : "l"(v));
}
__device__ __forceinline__ unsigned smem_u32(const void* p) {
    return (unsigned)__cvta_generic_to_shared(p);
}
__device__ __forceinline__ unsigned mapa_rank(unsigned local_addr, int rank) {
    unsigned r;
    asm("mapa.shared::cluster.u32 %0, %1, %2;" : "=r"(r) : "r"(local_addr), "r"(rank));
    return r;
}
__device__ __forceinline__ void st_cluster_v4(unsigned addr, float4 v) {
    asm volatile("st.shared::cluster.v4.b32 [%0], {%1, %2, %3, %4};"
                 :: "r"(addr), "f"(v.x), "f"(v.y), "f"(v.z), "f"(v.w) : "memory");
}
#define CLUSTER_ARRIVE() asm volatile("barrier.cluster.arrive.aligned;" ::: "memory")
#define CLUSTER_WAIT()   asm volatile("barrier.cluster.wait.aligned;"   ::: "memory")

// ---------- kernel 1: gated = xd * sigmoid(w)  (R6 exact) ----------
__global__ void __launch_bounds__(256) k_gate(const float* __restrict__ xd,
                                              const float* __restrict__ w) {
    size_t i = ((size_t)blockIdx.x * 256 + threadIdx.x) * 4;
    float4 x = __ldg((const float4*)(xd + i));
    float4 g = __ldg((const float4*)(w + i));
    float4 o;
    o.x = x.x * sigm(g.x);
    o.y = x.y * sigm(g.y);
    o.z = x.z * sigm(g.z);
    o.w = x.w * sigm(g.w);
    *(float4*)(g_gated + i) = o;
}

// ---------- kernel 2: x_part GEMM + fused bias  (R6 exact) ----------
__global__ void __launch_bounds__(256, 2) k_xpart(const float* __restrict__ Wih,
                                                  const float* __restrict__ bih,
                                                  const float* __restrict__ bhh) {
    __shared__ float As[32 * 132];   // [k][m] padded
    __shared__ float Bs[32 * 72];    // [k][n] padded

    const int tid = threadIdx.x;
    const int tx = tid & 15;
    const int ty = tid >> 4;
    const int m_base = blockIdx.y * 128;
    const int n_base = blockIdx.x * 64;

    unsigned long long acc[8][2];
#pragma unroll
    for (int i = 0; i < 8; ++i) { acc[i][0] = 0ull; acc[i][1] = 0ull; }

    const int am = tid & 127, ah = (tid >> 7) * 16;
    const int bn = tid & 63,  bh = (tid >> 6) * 8;
    const float* Ag = g_gated + (size_t)(m_base + am) * INDIM;
    const float* Bg = Wih + (size_t)(n_base + bn) * INDIM;

    for (int ks = 0; ks < 4; ++ks) {
        const int k0 = ks * 32;
#pragma unroll
        for (int u = 0; u < 4; ++u) {
            float4 v = __ldg((const float4*)(Ag + k0 + ah + u * 4));
            int k = ah + u * 4;
            As[(k + 0) * 132 + am] = v.x;
            As[(k + 1) * 132 + am] = v.y;
            As[(k + 2) * 132 + am] = v.z;
            As[(k + 3) * 132 + am] = v.w;
        }
#pragma unroll
        for (int u = 0; u < 2; ++u) {
            float4 v = __ldg((const float4*)(Bg + k0 + bh + u * 4));
            int k = bh + u * 4;
            Bs[(k + 0) * 72 + bn] = v.x;
            Bs[(k + 1) * 72 + bn] = v.y;
            Bs[(k + 2) * 72 + bn] = v.z;
            Bs[(k + 3) * 72 + bn] = v.w;
        }
        __syncthreads();
#pragma unroll
        for (int k = 0; k < 32; ++k) {
            const ulonglong2 bbv = *(const ulonglong2*)&Bs[k * 72 + tx * 4];
            const float4 a0 = *(const float4*)&As[k * 132 + ty * 8];
            const float4 a1 = *(const float4*)&As[k * 132 + ty * 8 + 4];
            float a[8] = {a0.x, a0.y, a0.z, a0.w, a1.x, a1.y, a1.z, a1.w};
#pragma unroll
            for (int i = 0; i < 8; ++i) {
                unsigned long long d = dup2(a[i]);
                ffma2(acc[i][0], d, bbv.x);
                ffma2(acc[i][1], d, bbv.y);
            }
        }
        __syncthreads();
    }

    const int col0 = n_base + tx * 4;
    float4 bias;
    bias.x = __ldg(bih + col0 + 0) + __ldg(bhh + col0 + 0);
    bias.y = __ldg(bih + col0 + 1) + __ldg(bhh + col0 + 1);
    bias.z = __ldg(bih + col0 + 2) + __ldg(bhh + col0 + 2);
    bias.w = __ldg(bih + col0 + 3) + __ldg(bhh + col0 + 3);
#pragma unroll
    for (int i = 0; i < 8; ++i) {
        int gm = m_base + ty * 8 + i;
        int b = gm >> 11;              // m = b*2048 + t
        int t = gm & 2047;
        float x0, x1, x2, x3;
        unpack2(acc[i][0], x0, x1);
        unpack2(acc[i][1], x2, x3);
        float4 o = make_float4(x0 + bias.x, x1 + bias.y, x2 + bias.z, x3 + bias.w);
        *(float4*)&g_xpart[((size_t)t * BATCH + b) * (4 * HID) + col0] = o;
    }
}

// ---------- kernel 3: LSTM recurrence (R6 step code, SINGLE launch) ----------
// 128 CTAs of 512 threads, clusters of 8 (rank jb = j-slice), bb = blockIdx>>3.
// Thread: rg = tid>>4 (local j), kc = tid&15 (16 k-slices, k = 2kc+32m, m<8).
// buf layout: [p][rank][b][j32]; exchange = one warp-wide 512B store per dest.
__global__ void __launch_bounds__(512, 1) __cluster_dims__(GJ, 1, 1)
k_rec(const float* __restrict__ Whh, int chunk) {
    const int tid = threadIdx.x;
    const int kc = tid & 15;
    const int rg = tid >> 4;
    unsigned jb;
    asm("mov.u32 %0, %%cluster_ctarank;" : "=r"(jb));
    const int bb = blockIdx.x >> 3;

    __shared__ __align__(16) float buf[2][GJ * 4 * 32];  // [p][rank][b][j] (2 x 4KB)
    __shared__ __align__(16) float xp_s[512];            // [b][g][j]
    __shared__ __align__(16) float staging[128];         // [b][j] local h slice

    // persistent W registers: w2[g][m] = (W[row][2kc+32m], W[row][2kc+32m+1])
    unsigned long long w2[4][8];
#pragma unroll
    for (int g = 0; g < 4; ++g) {
        const float* rp = Whh + (size_t)(g * HID + jb * 32 + rg) * HID + 2 * kc;
#pragma unroll
        for (int m = 0; m < 8; ++m)
            w2[g][m] = __ldg((const unsigned long long*)(rp + 32 * m));
    }

    // h(chunk start) into buf[0] in [rank][b][j] layout
#pragma unroll
    for (int i = tid; i < GJ * 4 * 32; i += 512) {
        int r = i >> 7, b = (i >> 5) & 3, j = i & 31;
        buf[0][i] = (chunk == 0) ? 0.f
                                 : __ldcg(&g_hst[bb * 1024 + b * HID + r * 32 + j]);
    }

    // owner cell state
    const int ob = kc & 3;                     // owner batch (valid when kc<4)
    const size_t cell = (size_t)bb * 1024 + (size_t)ob * HID + jb * 32 + rg;
    float c = 0.f;
    if (chunk != 0 && kc < 4) c = __ldcg(&g_cst[cell]);

    // copier setup: warp w<8 copies staging (512B) to dest rank w's buf slot
    const int wrp = tid >> 5, lane = tid & 31;
    unsigned rdst = 0;
    if (wrp < GJ)
        rdst = mapa_rank(smem_u32(&buf[0][0]), wrp) + jb * 512u + lane * 16u;

    __syncthreads();
    CLUSTER_ARRIVE();
    CLUSTER_WAIT();

    // xp mapping: tid = b*128 + g*32 + j  → xp_s[tid]
    const int t0 = chunk * CHUNK;
    const int xb = tid >> 7, xg = (tid >> 5) & 3, xj = tid & 31;
    const float* xptr = g_xpart + (size_t)(bb * 4 + xb) * (4 * HID) + xg * HID + jb * 32 + xj;
    float xp_pf = __ldg(xptr + (size_t)t0 * (BATCH * 4 * HID));

    const bool u1 = (kc & 1), u2 = (kc & 2), u4 = (kc & 4), u8 = (kc & 8);

    int p = 0;
    for (int t = 0; t < CHUNK; ++t) {
        // stage xp for this step (readers wait for the syncthreads below;
        // prior-step readers all passed last step's barriers, so no race)
        xp_s[tid] = xp_pf;

        // ---- z_hh partial GEMM over local h copy ----
        unsigned long long acc[4][4];
#pragma unroll
        for (int g = 0; g < 4; ++g)
#pragma unroll
            for (int b = 0; b < 4; ++b) acc[g][b] = 0ull;

        const float* hb = &buf[p][0];
#pragma unroll
        for (int m = 0; m < 8; ++m) {
#pragma unroll
            for (int b = 0; b < 4; ++b) {
                unsigned long long h2 =
                    *(const unsigned long long*)&hb[(m * 4 + b) * 32 + 2 * kc];
#pragma unroll
                for (int g = 0; g < 4; ++g) ffma2(acc[g][b], w2[g][m], h2);
            }
        }

        // ---- horizontal add: v[i], i = g*4+b ----
        float v[16];
#pragma unroll
        for (int g = 0; g < 4; ++g)
#pragma unroll
            for (int b = 0; b < 4; ++b) {
                float lo, hi;
                unpack2(acc[g][b], lo, hi);
                v[g * 4 + b] = lo + hi;
            }

        // ---- split-tree reduction over 16 kc lanes ----
        float u[8];
#pragma unroll
        for (int j = 0; j < 8; ++j) {
            float snd = u1 ? v[2 * j] : v[2 * j + 1];
            float kept = u1 ? v[2 * j + 1] : v[2 * j];
            u[j] = kept + __shfl_xor_sync(0xffffffffu, snd, 1);
        }
        float w4[4];
#pragma unroll
        for (int j = 0; j < 4; ++j) {
            float snd = u2 ? u[2 * j] : u[2 * j + 1];
            float kept = u2 ? u[2 * j + 1] : u[2 * j];
            w4[j] = kept + __shfl_xor_sync(0xffffffffu, snd, 2);
        }
        float x2[2];
#pragma unroll
        for (int j = 0; j < 2; ++j) {
            float snd = u4 ? w4[2 * j] : w4[2 * j + 1];
            float kept = u4 ? w4[2 * j + 1] : w4[2 * j];
            x2[j] = kept + __shfl_xor_sync(0xffffffffu, snd, 4);
        }
        float z;                                   // z[g=kc>>2][b=kc&3]
        {
            float snd = u8 ? x2[0] : x2[1];
            float kept = u8 ? x2[1] : x2[0];
            z = kept + __shfl_xor_sync(0xffffffffu, snd, 8);
        }
        // gather gates onto owner lanes (kc<4): i,f,g,o
        float t1 = __shfl_xor_sync(0xffffffffu, z, 4);
        float t2 = __shfl_xor_sync(0xffffffffu, z, 8);
        float t3 = __shfl_xor_sync(0xffffffffu, t1, 8);

        __syncthreads();   // sync#1: xp_s visible to owners

        // ---- cell update (owners) → local staging ----
        if (kc < 4) {
            float zi = z  + xp_s[(ob * 4 + 0) * 32 + rg];
            float zf = t1 + xp_s[(ob * 4 + 1) * 32 + rg];
            float zg = t2 + xp_s[(ob * 4 + 2) * 32 + rg];
            float zo = t3 + xp_s[(ob * 4 + 3) * 32 + rg];
            c = sigm(zf) * c + sigm(zi) * tanh_f(zg);
            float h = sigm(zo) * tanh_f(c);
            staging[ob * 32 + rg] = h;
            if (t == CHUNK - 1) {
                g_hst[cell] = h;
                g_cst[cell] = c;
            }
        }
        __syncthreads();   // sync#2: staging complete

        // ---- bulk exchange: warp w ships 512B slice to dest rank w ----
        if (wrp < GJ) {
            float4 hv = *(const float4*)&staging[lane * 4];
            st_cluster_v4(rdst + (unsigned)((p ^ 1) * (GJ * 4 * 32) * 4), hv);
        }

        // ---- barrier: arrive (releases copier stores), prefetch, wait ----
        CLUSTER_ARRIVE();
        {
            int tn = t0 + t + 1;
            if (tn > T_STEPS - 1) tn = T_STEPS - 1;
            xp_pf = __ldg(xptr + (size_t)tn * (BATCH * 4 * HID));
        }
        CLUSTER_WAIT();
        p ^= 1;
    }
}

// ---------- kernel 4: out[b] = h_T[b] @ W_out^T + b_out ----------
__global__ void __launch_bounds__(256) k_out(const float* __restrict__ Wout,
                                             const float* __restrict__ bout,
                                             float* __restrict__ out) {
    const int b = blockIdx.x;
    const int tid = threadIdx.x;
    float v = g_hst[b * HID + tid] * __ldg(Wout + tid);
#pragma unroll
    for (int d = 16; d >= 1; d >>= 1) v += __shfl_xor_sync(0xffffffffu, v, d);
    __shared__ float s[8];
    if ((tid & 31) == 0) s[tid >> 5] = v;
    __syncthreads();
    if (tid == 0) {
        float acc = 0.f;
#pragma unroll
        for (int i = 0; i < 8; ++i) acc += s[i];
        out[b] = acc + __ldg(bout);
    }
}

// ---------- launch ----------
extern "C" void kernel_launch(void* const* d_in, const int* in_sizes, int n_in,
                              void* d_out, int out_size) {
    const float* xd   = (const float*)d_in[0];
    const float* w    = (const float*)d_in[1];
    const float* Wih  = (const float*)d_in[2];
    const float* bih  = (const float*)d_in[3];
    const float* Whh  = (const float*)d_in[4];
    const float* bhh  = (const float*)d_in[5];
    const float* Wout = (const float*)d_in[6];
    const float* bout = (const float*)d_in[7];
    float* out = (float*)d_out;

    k_gate<<<(BATCH * T_STEPS * INDIM) / (256 * 4), 256>>>(xd, w);

    dim3 gx(1024 / 64, (BATCH * T_STEPS) / 128);
    k_xpart<<<gx, 256>>>(Wih, bih, bhh);

    for (int c = 0; c < NCHUNK; ++c)
        k_rec<<<GJ * GB, 512>>>(Whh, c);   // single launch (NCHUNK == 1)

    k_out<<<BATCH, 256>>>(Wout, bout, out);
}

// round 15
// speedup vs baseline: 1.3058x; 1.0041x over previous
#include <cuda_runtime.h>
#include <cuda_bf16.h>
#include <cstdint>
#include <cstddef>

#define T_STEPS 2048
#define BATCH   64
#define HID     256
#define INDIM   128
#define GJ      8      // j-slices per cluster (32 hidden units each)
#define GB      16     // batch-blocks (4 batches each)
#define CHUNK   2048   // single launch: all steps in one k_rec
#define NCHUNK  (T_STEPS / CHUNK)

// ---- scratch (device globals: allocation-free rule) ----
__device__ __align__(16) float g_gated[(size_t)BATCH * T_STEPS * INDIM];       // 64 MB
__device__ __align__(16) float g_xpart[(size_t)T_STEPS * BATCH * 4 * HID];     // 512 MB
__device__ __align__(16) float g_hst[BATCH * HID];   // final h
__device__ __align__(16) float g_cst[BATCH * HID];   // (unused in single-chunk mode)

// ---------- helpers ----------
__device__ __forceinline__ float sigm(float x) {
    return __fdividef(1.f, 1.f + __expf(-x));
}
__device__ __forceinline__ float tanh_f(float x) {
    float e = __expf(2.f * x);
    return 1.f - __fdividef(2.f, e + 1.f);   // exact limits at +/-inf
}
__device__ __forceinline__ void ffma2(unsigned long long& d, unsigned long long a,
                                      unsigned long long b) {
    asm("fma.rn.f32x2 %0, %1, %2, %0;" : "+l"(d) : "l"(a), "l"(b));
}
__device__ __forceinline__ unsigned long long dup2(float x) {
    unsigned long long r;
    asm("mov.b64 %0, {%1, %1};" : "=l"(r) : "f"(x));
    return r;
}
__device__ __forceinline__ void unpack2(unsigned long long v, float& x, float& y) {
    asm("mov.b64 {%0, %1}, %2;" : "=f"(x), "=f"(y) : "l"(v));
}
__device__ __forceinline__ unsigned smem_u32(const void* p) {
    return (unsigned)__cvta_generic_to_shared(p);
}
__device__ __forceinline__ unsigned mapa_rank(unsigned local_addr, int rank) {
    unsigned r;
    asm("mapa.shared::cluster.u32 %0, %1, %2;" : "=r"(r) : "r"(local_addr), "r"(rank));
    return r;
}
__device__ __forceinline__ void st_cluster_v4(unsigned addr, float4 v) {
    asm volatile("st.shared::cluster.v4.b32 [%0], {%1, %2, %3, %4};"
                 :: "r"(addr), "f"(v.x), "f"(v.y), "f"(v.z), "f"(v.w) : "memory");
}
#define CLUSTER_ARRIVE() asm volatile("barrier.cluster.arrive.aligned;" ::: "memory")
#define CLUSTER_WAIT()   asm volatile("barrier.cluster.wait.aligned;"   ::: "memory")

// ---------- kernel 1: gated = xd * sigmoid(w)  (champion exact) ----------
__global__ void __launch_bounds__(256) k_gate(const float* __restrict__ xd,
                                              const float* __restrict__ w) {
    size_t i = ((size_t)blockIdx.x * 256 + threadIdx.x) * 4;
    float4 x = __ldg((const float4*)(xd + i));
    float4 g = __ldg((const float4*)(w + i));
    float4 o;
    o.x = x.x * sigm(g.x);
    o.y = x.y * sigm(g.y);
    o.z = x.z * sigm(g.z);
    o.w = x.w * sigm(g.w);
    *(float4*)(g_gated + i) = o;
}

// ---------- kernel 2: x_part GEMM + fused bias  (champion + occ 3) ----------
__global__ void __launch_bounds__(256, 3) k_xpart(const float* __restrict__ Wih,
                                                  const float* __restrict__ bih,
                                                  const float* __restrict__ bhh) {
    __shared__ float As[32 * 132];   // [k][m] padded
    __shared__ float Bs[32 * 72];    // [k][n] padded

    const int tid = threadIdx.x;
    const int tx = tid & 15;
    const int ty = tid >> 4;
    const int m_base = blockIdx.y * 128;
    const int n_base = blockIdx.x * 64;

    unsigned long long acc[8][2];
#pragma unroll
    for (int i = 0; i < 8; ++i) { acc[i][0] = 0ull; acc[i][1] = 0ull; }

    const int am = tid & 127, ah = (tid >> 7) * 16;
    const int bn = tid & 63,  bh = (tid >> 6) * 8;
    const float* Ag = g_gated + (size_t)(m_base + am) * INDIM;
    const float* Bg = Wih + (size_t)(n_base + bn) * INDIM;

    for (int ks = 0; ks < 4; ++ks) {
        const int k0 = ks * 32;
#pragma unroll
        for (int u = 0; u < 4; ++u) {
            float4 v = __ldg((const float4*)(Ag + k0 + ah + u * 4));
            int k = ah + u * 4;
            As[(k + 0) * 132 + am] = v.x;
            As[(k + 1) * 132 + am] = v.y;
            As[(k + 2) * 132 + am] = v.z;
            As[(k + 3) * 132 + am] = v.w;
        }
#pragma unroll
        for (int u = 0; u < 2; ++u) {
            float4 v = __ldg((const float4*)(Bg + k0 + bh + u * 4));
            int k = bh + u * 4;
            Bs[(k + 0) * 72 + bn] = v.x;
            Bs[(k + 1) * 72 + bn] = v.y;
            Bs[(k + 2) * 72 + bn] = v.z;
            Bs[(k + 3) * 72 + bn] = v.w;
        }
        __syncthreads();
#pragma unroll
        for (int k = 0; k < 32; ++k) {
            const ulonglong2 bbv = *(const ulonglong2*)&Bs[k * 72 + tx * 4];
            const float4 a0 = *(const float4*)&As[k * 132 + ty * 8];
            const float4 a1 = *(const float4*)&As[k * 132 + ty * 8 + 4];
            float a[8] = {a0.x, a0.y, a0.z, a0.w, a1.x, a1.y, a1.z, a1.w};
#pragma unroll
            for (int i = 0; i < 8; ++i) {
                unsigned long long d = dup2(a[i]);
                ffma2(acc[i][0], d, bbv.x);
                ffma2(acc[i][1], d, bbv.y);
            }
        }
        __syncthreads();
    }

    const int col0 = n_base + tx * 4;
    float4 bias;
    bias.x = __ldg(bih + col0 + 0) + __ldg(bhh + col0 + 0);
    bias.y = __ldg(bih + col0 + 1) + __ldg(bhh + col0 + 1);
    bias.z = __ldg(bih + col0 + 2) + __ldg(bhh + col0 + 2);
    bias.w = __ldg(bih + col0 + 3) + __ldg(bhh + col0 + 3);
#pragma unroll
    for (int i = 0; i < 8; ++i) {
        int gm = m_base + ty * 8 + i;
        int b = gm >> 11;              // m = b*2048 + t
        int t = gm & 2047;
        float x0, x1, x2, x3;
        unpack2(acc[i][0], x0, x1);
        unpack2(acc[i][1], x2, x3);
        float4 o = make_float4(x0 + bias.x, x1 + bias.y, x2 + bias.z, x3 + bias.w);
        *(float4*)&g_xpart[((size_t)t * BATCH + b) * (4 * HID) + col0] = o;
    }
}

// ---------- kernel 3: LSTM recurrence (champion exact, single launch) ----------
// 128 CTAs of 512 threads, clusters of 8 (rank jb = j-slice), bb = blockIdx>>3.
// Thread: rg = tid>>4 (local j), kc = tid&15 (16 k-slices, k = 2kc+32m, m<8).
// buf layout: [p][rank][b][j32]; exchange = one warp-wide 512B store per dest.
__global__ void __launch_bounds__(512, 1) __cluster_dims__(GJ, 1, 1)
k_rec(const float* __restrict__ Whh, int chunk) {
    const int tid = threadIdx.x;
    const int kc = tid & 15;
    const int rg = tid >> 4;
    unsigned jb;
    asm("mov.u32 %0, %%cluster_ctarank;" : "=r"(jb));
    const int bb = blockIdx.x >> 3;

    __shared__ __align__(16) float buf[2][GJ * 4 * 32];  // [p][rank][b][j] (2 x 4KB)
    __shared__ __align__(16) float xp_s[512];            // [b][g][j]
    __shared__ __align__(16) float staging[128];         // [b][j] local h slice

    // persistent W registers: w2[g][m] = (W[row][2kc+32m], W[row][2kc+32m+1])
    unsigned long long w2[4][8];
#pragma unroll
    for (int g = 0; g < 4; ++g) {
        const float* rp = Whh + (size_t)(g * HID + jb * 32 + rg) * HID + 2 * kc;
#pragma unroll
        for (int m = 0; m < 8; ++m)
            w2[g][m] = __ldg((const unsigned long long*)(rp + 32 * m));
    }

    // h(chunk start) into buf[0] in [rank][b][j] layout
#pragma unroll
    for (int i = tid; i < GJ * 4 * 32; i += 512) {
        int r = i >> 7, b = (i >> 5) & 3, j = i & 31;
        buf[0][i] = (chunk == 0) ? 0.f
                                 : __ldcg(&g_hst[bb * 1024 + b * HID + r * 32 + j]);
    }

    // owner cell state
    const int ob = kc & 3;                     // owner batch (valid when kc<4)
    const size_t cell = (size_t)bb * 1024 + (size_t)ob * HID + jb * 32 + rg;
    float c = 0.f;
    if (chunk != 0 && kc < 4) c = __ldcg(&g_cst[cell]);

    // copier setup: warp w<8 copies staging (512B) to dest rank w's buf slot
    const int wrp = tid >> 5, lane = tid & 31;
    unsigned rdst = 0;
    if (wrp < GJ)
        rdst = mapa_rank(smem_u32(&buf[0][0]), wrp) + jb * 512u + lane * 16u;

    __syncthreads();
    CLUSTER_ARRIVE();
    CLUSTER_WAIT();

    // xp mapping: tid = b*128 + g*32 + j  → xp_s[tid]
    const int t0 = chunk * CHUNK;
    const int xb = tid >> 7, xg = (tid >> 5) & 3, xj = tid & 31;
    const float* xptr = g_xpart + (size_t)(bb * 4 + xb) * (4 * HID) + xg * HID + jb * 32 + xj;
    float xp_pf = __ldg(xptr + (size_t)t0 * (BATCH * 4 * HID));

    const bool u1 = (kc & 1), u2 = (kc & 2), u4 = (kc & 4), u8 = (kc & 8);

    int p = 0;
    for (int t = 0; t < CHUNK; ++t) {
        // stage xp for this step (readers wait for the syncthreads below;
        // prior-step readers all passed last step's barriers, so no race)
        xp_s[tid] = xp_pf;

        // ---- z_hh partial GEMM over local h copy ----
        unsigned long long acc[4][4];
#pragma unroll
        for (int g = 0; g < 4; ++g)
#pragma unroll
            for (int b = 0; b < 4; ++b) acc[g][b] = 0ull;

        const float* hb = &buf[p][0];
#pragma unroll
        for (int m = 0; m < 8; ++m) {
#pragma unroll
            for (int b = 0; b < 4; ++b) {
                unsigned long long h2 =
                    *(const unsigned long long*)&hb[(m * 4 + b) * 32 + 2 * kc];
#pragma unroll
                for (int g = 0; g < 4; ++g) ffma2(acc[g][b], w2[g][m], h2);
            }
        }

        // ---- horizontal add: v[i], i = g*4+b ----
        float v[16];
#pragma unroll
        for (int g = 0; g < 4; ++g)
#pragma unroll
            for (int b = 0; b < 4; ++b) {
                float lo, hi;
                unpack2(acc[g][b], lo, hi);
                v[g * 4 + b] = lo + hi;
            }

        // ---- split-tree reduction over 16 kc lanes ----
        float u[8];
#pragma unroll
        for (int j = 0; j < 8; ++j) {
            float snd = u1 ? v[2 * j] : v[2 * j + 1];
            float kept = u1 ? v[2 * j + 1] : v[2 * j];
            u[j] = kept + __shfl_xor_sync(0xffffffffu, snd, 1);
        }
        float w4[4];
#pragma unroll
        for (int j = 0; j < 4; ++j) {
            float snd = u2 ? u[2 * j] : u[2 * j + 1];
            float kept = u2 ? u[2 * j + 1] : u[2 * j];
            w4[j] = kept + __shfl_xor_sync(0xffffffffu, snd, 2);
        }
        float x2[2];
#pragma unroll
        for (int j = 0; j < 2; ++j) {
            float snd = u4 ? w4[2 * j] : w4[2 * j + 1];
            float kept = u4 ? w4[2 * j + 1] : w4[2 * j];
            x2[j] = kept + __shfl_xor_sync(0xffffffffu, snd, 4);
        }
        float z;                                   // z[g=kc>>2][b=kc&3]
        {
            float snd = u8 ? x2[0] : x2[1];
            float kept = u8 ? x2[1] : x2[0];
            z = kept + __shfl_xor_sync(0xffffffffu, snd, 8);
        }
        // gather gates onto owner lanes (kc<4): i,f,g,o
        float t1 = __shfl_xor_sync(0xffffffffu, z, 4);
        float t2 = __shfl_xor_sync(0xffffffffu, z, 8);
        float t3 = __shfl_xor_sync(0xffffffffu, t1, 8);

        __syncthreads();   // sync#1: xp_s visible to owners

        // ---- cell update (owners) → local staging ----
        if (kc < 4) {
            float zi = z  + xp_s[(ob * 4 + 0) * 32 + rg];
            float zf = t1 + xp_s[(ob * 4 + 1) * 32 + rg];
            float zg = t2 + xp_s[(ob * 4 + 2) * 32 + rg];
            float zo = t3 + xp_s[(ob * 4 + 3) * 32 + rg];
            c = sigm(zf) * c + sigm(zi) * tanh_f(zg);
            float h = sigm(zo) * tanh_f(c);
            staging[ob * 32 + rg] = h;
            if (t == CHUNK - 1) {
                g_hst[cell] = h;
                g_cst[cell] = c;
            }
        }
        __syncthreads();   // sync#2: staging complete

        // ---- bulk exchange: warp w ships 512B slice to dest rank w ----
        if (wrp < GJ) {
            float4 hv = *(const float4*)&staging[lane * 4];
            st_cluster_v4(rdst + (unsigned)((p ^ 1) * (GJ * 4 * 32) * 4), hv);
        }

        // ---- barrier: arrive (releases copier stores), prefetch, wait ----
        CLUSTER_ARRIVE();
        {
            int tn = t0 + t + 1;
            if (tn > T_STEPS - 1) tn = T_STEPS - 1;
            xp_pf = __ldg(xptr + (size_t)tn * (BATCH * 4 * HID));
        }
        CLUSTER_WAIT();
        p ^= 1;
    }
}

// ---------- kernel 4: out[b] = h_T[b] @ W_out^T + b_out ----------
__global__ void __launch_bounds__(256) k_out(const float* __restrict__ Wout,
                                             const float* __restrict__ bout,
                                             float* __restrict__ out) {
    const int b = blockIdx.x;
    const int tid = threadIdx.x;
    float v = g_hst[b * HID + tid] * __ldg(Wout + tid);
#pragma unroll
    for (int d = 16; d >= 1; d >>= 1) v += __shfl_xor_sync(0xffffffffu, v, d);
    __shared__ float s[8];
    if ((tid & 31) == 0) s[tid >> 5] = v;
    __syncthreads();
    if (tid == 0) {
        float acc = 0.f;
#pragma unroll
        for (int i = 0; i < 8; ++i) acc += s[i];
        out[b] = acc + __ldg(bout);
    }
}

// ---------- launch ----------
extern "C" void kernel_launch(void* const* d_in, const int* in_sizes, int n_in,
                              void* d_out, int out_size) {
    const float* xd   = (const float*)d_in[0];
    const float* w    = (const float*)d_in[1];
    const float* Wih  = (const float*)d_in[2];
    const float* bih  = (const float*)d_in[3];
    const float* Whh  = (const float*)d_in[4];
    const float* bhh  = (const float*)d_in[5];
    const float* Wout = (const float*)d_in[6];
    const float* bout = (const float*)d_in[7];
    float* out = (float*)d_out;

    k_gate<<<(BATCH * T_STEPS * INDIM) / (256 * 4), 256>>>(xd, w);

    dim3 gx(1024 / 64, (BATCH * T_STEPS) / 128);
    k_xpart<<<gx, 256>>>(Wih, bih, bhh);

    for (int c = 0; c < NCHUNK; ++c)
        k_rec<<<GJ * GB, 512>>>(Whh, c);   // single launch (NCHUNK == 1)

    k_out<<<BATCH, 256>>>(Wout, bout, out);
}

// round 16
// speedup vs baseline: 1.3079x; 1.0016x over previous
#include <cuda_runtime.h>
#include <cuda_bf16.h>
#include <cstdint>
#include <cstddef>

#define T_STEPS 2048
#define BATCH   64
#define HID     256
#define INDIM   128
#define GJ      8      // j-slices per cluster (32 hidden units each)
#define GB      16     // batch-blocks (4 batches each)
#define CHUNK   2048   // single launch: all steps in one k_rec
#define NCHUNK  (T_STEPS / CHUNK)

// ---- scratch (device globals: allocation-free rule) ----
__device__ __align__(16) float g_gated[(size_t)BATCH * T_STEPS * INDIM];       // 64 MB
__device__ __align__(16) float g_xpart[(size_t)T_STEPS * BATCH * 4 * HID];     // 512 MB
__device__ __align__(16) float g_hst[BATCH * HID];   // final h
__device__ __align__(16) float g_cst[BATCH * HID];   // (unused in single-chunk mode)

// ---------- helpers ----------
__device__ __forceinline__ float sigm(float x) {
    return __fdividef(1.f, 1.f + __expf(-x));
}
__device__ __forceinline__ float tanh_f(float x) {
    float e = __expf(2.f * x);
    return 1.f - __fdividef(2.f, e + 1.f);   // exact limits at +/-inf
}
__device__ __forceinline__ void ffma2(unsigned long long& d, unsigned long long a,
                                      unsigned long long b) {
    asm("fma.rn.f32x2 %0, %1, %2, %0;" : "+l"(d) : "l"(a), "l"(b));
}
__device__ __forceinline__ unsigned long long dup2(float x) {
    unsigned long long r;
    asm("mov.b64 %0, {%1, %1};" : "=l"(r) : "f"(x));
    return r;
}
__device__ __forceinline__ void unpack2(unsigned long long v, float& x, float& y) {
    asm("mov.b64 {%0, %1}, %2;" : "=f"(x), "=f"(y) : "l"(v));
}
__device__ __forceinline__ unsigned smem_u32(const void* p) {
    return (unsigned)__cvta_generic_to_shared(p);
}
__device__ __forceinline__ unsigned mapa_rank(unsigned local_addr, int rank) {
    unsigned r;
    asm("mapa.shared::cluster.u32 %0, %1, %2;" : "=r"(r) : "r"(local_addr), "r"(rank));
    return r;
}
__device__ __forceinline__ void st_cluster_v4(unsigned addr, float4 v) {
    asm volatile("st.shared::cluster.v4.b32 [%0], {%1, %2, %3, %4};"
                 :: "r"(addr), "f"(v.x), "f"(v.y), "f"(v.z), "f"(v.w) : "memory");
}
#define CLUSTER_ARRIVE() asm volatile("barrier.cluster.arrive.aligned;" ::: "memory")
#define CLUSTER_WAIT()   asm volatile("barrier.cluster.wait.aligned;"   ::: "memory")

// ---------- kernel 1: gated = xd * sigmoid(w)  (champion exact) ----------
__global__ void __launch_bounds__(256) k_gate(const float* __restrict__ xd,
                                              const float* __restrict__ w) {
    size_t i = ((size_t)blockIdx.x * 256 + threadIdx.x) * 4;
    float4 x = __ldg((const float4*)(xd + i));
    float4 g = __ldg((const float4*)(w + i));
    float4 o;
    o.x = x.x * sigm(g.x);
    o.y = x.y * sigm(g.y);
    o.z = x.z * sigm(g.z);
    o.w = x.w * sigm(g.w);
    *(float4*)(g_gated + i) = o;
}

// ---------- kernel 2: x_part GEMM + fused bias  (champion + occ 3) ----------
__global__ void __launch_bounds__(256, 3) k_xpart(const float* __restrict__ Wih,
                                                  const float* __restrict__ bih,
                                                  const float* __restrict__ bhh) {
    __shared__ float As[32 * 132];   // [k][m] padded
    __shared__ float Bs[32 * 72];    // [k][n] padded

    const int tid = threadIdx.x;
    const int tx = tid & 15;
    const int ty = tid >> 4;
    const int m_base = blockIdx.y * 128;
    const int n_base = blockIdx.x * 64;

    unsigned long long acc[8][2];
#pragma unroll
    for (int i = 0; i < 8; ++i) { acc[i][0] = 0ull; acc[i][1] = 0ull; }

    const int am = tid & 127, ah = (tid >> 7) * 16;
    const int bn = tid & 63,  bh = (tid >> 6) * 8;
    const float* Ag = g_gated + (size_t)(m_base + am) * INDIM;
    const float* Bg = Wih + (size_t)(n_base + bn) * INDIM;

    for (int ks = 0; ks < 4; ++ks) {
        const int k0 = ks * 32;
#pragma unroll
        for (int u = 0; u < 4; ++u) {
            float4 v = __ldg((const float4*)(Ag + k0 + ah + u * 4));
            int k = ah + u * 4;
            As[(k + 0) * 132 + am] = v.x;
            As[(k + 1) * 132 + am] = v.y;
            As[(k + 2) * 132 + am] = v.z;
            As[(k + 3) * 132 + am] = v.w;
        }
#pragma unroll
        for (int u = 0; u < 2; ++u) {
            float4 v = __ldg((const float4*)(Bg + k0 + bh + u * 4));
            int k = bh + u * 4;
            Bs[(k + 0) * 72 + bn] = v.x;
            Bs[(k + 1) * 72 + bn] = v.y;
            Bs[(k + 2) * 72 + bn] = v.z;
            Bs[(k + 3) * 72 + bn] = v.w;
        }
        __syncthreads();
#pragma unroll
        for (int k = 0; k < 32; ++k) {
            const ulonglong2 bbv = *(const ulonglong2*)&Bs[k * 72 + tx * 4];
            const float4 a0 = *(const float4*)&As[k * 132 + ty * 8];
            const float4 a1 = *(const float4*)&As[k * 132 + ty * 8 + 4];
            float a[8] = {a0.x, a0.y, a0.z, a0.w, a1.x, a1.y, a1.z, a1.w};
#pragma unroll
            for (int i = 0; i < 8; ++i) {
                unsigned long long d = dup2(a[i]);
                ffma2(acc[i][0], d, bbv.x);
                ffma2(acc[i][1], d, bbv.y);
            }
        }
        __syncthreads();
    }

    const int col0 = n_base + tx * 4;
    float4 bias;
    bias.x = __ldg(bih + col0 + 0) + __ldg(bhh + col0 + 0);
    bias.y = __ldg(bih + col0 + 1) + __ldg(bhh + col0 + 1);
    bias.z = __ldg(bih + col0 + 2) + __ldg(bhh + col0 + 2);
    bias.w = __ldg(bih + col0 + 3) + __ldg(bhh + col0 + 3);
#pragma unroll
    for (int i = 0; i < 8; ++i) {
        int gm = m_base + ty * 8 + i;
        int b = gm >> 11;              // m = b*2048 + t
        int t = gm & 2047;
        float x0, x1, x2, x3;
        unpack2(acc[i][0], x0, x1);
        unpack2(acc[i][1], x2, x3);
        float4 o = make_float4(x0 + bias.x, x1 + bias.y, x2 + bias.z, x3 + bias.w);
        *(float4*)&g_xpart[((size_t)t * BATCH + b) * (4 * HID) + col0] = o;
    }
}

// ---------- kernel 3: LSTM recurrence (champion exact, single launch) ----------
// 128 CTAs of 512 threads, clusters of 8 (rank jb = j-slice), bb = blockIdx>>3.
// Thread: rg = tid>>4 (local j), kc = tid&15 (16 k-slices, k = 2kc+32m, m<8).
// buf layout: [p][rank][b][j32]; exchange = one warp-wide 512B store per dest.
__global__ void __launch_bounds__(512, 1) __cluster_dims__(GJ, 1, 1)
k_rec(const float* __restrict__ Whh, int chunk) {
    const int tid = threadIdx.x;
    const int kc = tid & 15;
    const int rg = tid >> 4;
    unsigned jb;
    asm("mov.u32 %0, %%cluster_ctarank;" : "=r"(jb));
    const int bb = blockIdx.x >> 3;

    __shared__ __align__(16) float buf[2][GJ * 4 * 32];  // [p][rank][b][j] (2 x 4KB)
    __shared__ __align__(16) float xp_s[512];            // [b][g][j]
    __shared__ __align__(16) float staging[128];         // [b][j] local h slice

    // persistent W registers: w2[g][m] = (W[row][2kc+32m], W[row][2kc+32m+1])
    unsigned long long w2[4][8];
#pragma unroll
    for (int g = 0; g < 4; ++g) {
        const float* rp = Whh + (size_t)(g * HID + jb * 32 + rg) * HID + 2 * kc;
#pragma unroll
        for (int m = 0; m < 8; ++m)
            w2[g][m] = __ldg((const unsigned long long*)(rp + 32 * m));
    }

    // h(chunk start) into buf[0] in [rank][b][j] layout
#pragma unroll
    for (int i = tid; i < GJ * 4 * 32; i += 512) {
        int r = i >> 7, b = (i >> 5) & 3, j = i & 31;
        buf[0][i] = (chunk == 0) ? 0.f
                                 : __ldcg(&g_hst[bb * 1024 + b * HID + r * 32 + j]);
    }

    // owner cell state
    const int ob = kc & 3;                     // owner batch (valid when kc<4)
    const size_t cell = (size_t)bb * 1024 + (size_t)ob * HID + jb * 32 + rg;
    float c = 0.f;
    if (chunk != 0 && kc < 4) c = __ldcg(&g_cst[cell]);

    // copier setup: warp w<8 copies staging (512B) to dest rank w's buf slot
    const int wrp = tid >> 5, lane = tid & 31;
    unsigned rdst = 0;
    if (wrp < GJ)
        rdst = mapa_rank(smem_u32(&buf[0][0]), wrp) + jb * 512u + lane * 16u;

    __syncthreads();
    CLUSTER_ARRIVE();
    CLUSTER_WAIT();

    // xp mapping: tid = b*128 + g*32 + j  → xp_s[tid]
    const int t0 = chunk * CHUNK;
    const int xb = tid >> 7, xg = (tid >> 5) & 3, xj = tid & 31;
    const float* xptr = g_xpart + (size_t)(bb * 4 + xb) * (4 * HID) + xg * HID + jb * 32 + xj;
    float xp_pf = __ldg(xptr + (size_t)t0 * (BATCH * 4 * HID));

    const bool u1 = (kc & 1), u2 = (kc & 2), u4 = (kc & 4), u8 = (kc & 8);

    int p = 0;
    for (int t = 0; t < CHUNK; ++t) {
        // stage xp for this step (readers wait for the syncthreads below;
        // prior-step readers all passed last step's barriers, so no race)
        xp_s[tid] = xp_pf;

        // ---- z_hh partial GEMM over local h copy ----
        unsigned long long acc[4][4];
#pragma unroll
        for (int g = 0; g < 4; ++g)
#pragma unroll
            for (int b = 0; b < 4; ++b) acc[g][b] = 0ull;

        const float* hb = &buf[p][0];
#pragma unroll
        for (int m = 0; m < 8; ++m) {
#pragma unroll
            for (int b = 0; b < 4; ++b) {
                unsigned long long h2 =
                    *(const unsigned long long*)&hb[(m * 4 + b) * 32 + 2 * kc];
#pragma unroll
                for (int g = 0; g < 4; ++g) ffma2(acc[g][b], w2[g][m], h2);
            }
        }

        // ---- horizontal add: v[i], i = g*4+b ----
        float v[16];
#pragma unroll
        for (int g = 0; g < 4; ++g)
#pragma unroll
            for (int b = 0; b < 4; ++b) {
                float lo, hi;
                unpack2(acc[g][b], lo, hi);
                v[g * 4 + b] = lo + hi;
            }

        // ---- split-tree reduction over 16 kc lanes ----
        float u[8];
#pragma unroll
        for (int j = 0; j < 8; ++j) {
            float snd = u1 ? v[2 * j] : v[2 * j + 1];
            float kept = u1 ? v[2 * j + 1] : v[2 * j];
            u[j] = kept + __shfl_xor_sync(0xffffffffu, snd, 1);
        }
        float w4[4];
#pragma unroll
        for (int j = 0; j < 4; ++j) {
            float snd = u2 ? u[2 * j] : u[2 * j + 1];
            float kept = u2 ? u[2 * j + 1] : u[2 * j];
            w4[j] = kept + __shfl_xor_sync(0xffffffffu, snd, 2);
        }
        float x2[2];
#pragma unroll
        for (int j = 0; j < 2; ++j) {
            float snd = u4 ? w4[2 * j] : w4[2 * j + 1];
            float kept = u4 ? w4[2 * j + 1] : w4[2 * j];
            x2[j] = kept + __shfl_xor_sync(0xffffffffu, snd, 4);
        }
        float z;                                   // z[g=kc>>2][b=kc&3]
        {
            float snd = u8 ? x2[0] : x2[1];
            float kept = u8 ? x2[1] : x2[0];
            z = kept + __shfl_xor_sync(0xffffffffu, snd, 8);
        }
        // gather gates onto owner lanes (kc<4): i,f,g,o
        float t1 = __shfl_xor_sync(0xffffffffu, z, 4);
        float t2 = __shfl_xor_sync(0xffffffffu, z, 8);
        float t3 = __shfl_xor_sync(0xffffffffu, t1, 8);

        __syncthreads();   // sync#1: xp_s visible to owners

        // ---- cell update (owners) → local staging ----
        if (kc < 4) {
            float zi = z  + xp_s[(ob * 4 + 0) * 32 + rg];
            float zf = t1 + xp_s[(ob * 4 + 1) * 32 + rg];
            float zg = t2 + xp_s[(ob * 4 + 2) * 32 + rg];
            float zo = t3 + xp_s[(ob * 4 + 3) * 32 + rg];
            c = sigm(zf) * c + sigm(zi) * tanh_f(zg);
            float h = sigm(zo) * tanh_f(c);
            staging[ob * 32 + rg] = h;
            if (t == CHUNK - 1) {
                g_hst[cell] = h;
                g_cst[cell] = c;
            }
        }
        __syncthreads();   // sync#2: staging complete

        // ---- bulk exchange: warp w ships 512B slice to dest rank w ----
        if (wrp < GJ) {
            float4 hv = *(const float4*)&staging[lane * 4];
            st_cluster_v4(rdst + (unsigned)((p ^ 1) * (GJ * 4 * 32) * 4), hv);
        }

        // ---- barrier: arrive (releases copier stores), prefetch, wait ----
        CLUSTER_ARRIVE();
        {
            int tn = t0 + t + 1;
            if (tn > T_STEPS - 1) tn = T_STEPS - 1;
            xp_pf = __ldg(xptr + (size_t)tn * (BATCH * 4 * HID));
        }
        CLUSTER_WAIT();
        p ^= 1;
    }
}

// ---------- kernel 4: out[b] = h_T[b] @ W_out^T + b_out ----------
__global__ void __launch_bounds__(256) k_out(const float* __restrict__ Wout,
                                             const float* __restrict__ bout,
                                             float* __restrict__ out) {
    const int b = blockIdx.x;
    const int tid = threadIdx.x;
    float v = g_hst[b * HID + tid] * __ldg(Wout + tid);
#pragma unroll
    for (int d = 16; d >= 1; d >>= 1) v += __shfl_xor_sync(0xffffffffu, v, d);
    __shared__ float s[8];
    if ((tid & 31) == 0) s[tid >> 5] = v;
    __syncthreads();
    if (tid == 0) {
        float acc = 0.f;
#pragma unroll
        for (int i = 0; i < 8; ++i) acc += s[i];
        out[b] = acc + __ldg(bout);
    }
}

// ---------- launch ----------
extern "C" void kernel_launch(void* const* d_in, const int* in_sizes, int n_in,
                              void* d_out, int out_size) {
    const float* xd   = (const float*)d_in[0];
    const float* w    = (const float*)d_in[1];
    const float* Wih  = (const float*)d_in[2];
    const float* bih  = (const float*)d_in[3];
    const float* Whh  = (const float*)d_in[4];
    const float* bhh  = (const float*)d_in[5];
    const float* Wout = (const float*)d_in[6];
    const float* bout = (const float*)d_in[7];
    float* out = (float*)d_out;

    k_gate<<<(BATCH * T_STEPS * INDIM) / (256 * 4), 256>>>(xd, w);

    dim3 gx(1024 / 64, (BATCH * T_STEPS) / 128);
    k_xpart<<<gx, 256>>>(Wih, bih, bhh);

    for (int c = 0; c < NCHUNK; ++c)
        k_rec<<<GJ * GB, 512>>>(Whh, c);   // single launch (NCHUNK == 1)

    k_out<<<BATCH, 256>>>(Wout, bout, out);
}